// round 7
// baseline (speedup 1.0000x reference)
#include <cuda_runtime.h>
#include <cuda_fp16.h>
#include <math.h>

// ---------------------------------------------------------------------------
// 16-qubit statevector, batch 512. circuit qubit i <-> index bit (15-i).
// Layer = 16 one-qubit gates + CNOT-ladder = suffix-XOR permutation.
// State between passes: __half2(re,im), fp32 compute (f32x2 packed FMA).
// Batch processed in 2 chunks of 256 so the 64MB chunk state stays L2-resident
// across the chunk's launches.
// ---------------------------------------------------------------------------

#define TPB 512
#define BAT 512
#define CHUNK 256

typedef unsigned long long u64;

__device__ __half2 g_st[(size_t)BAT * 65536];
__device__ float   g_part[BAT * 8 * 16];

// ---------------- packed f32x2 helpers ----------------
__device__ __forceinline__ u64 pk2(float x, float y) {
    u64 r; asm("mov.b64 %0,{%1,%2};" : "=l"(r) : "f"(x), "f"(y)); return r;
}
__device__ __forceinline__ void upk2(u64 v, float& x, float& y) {
    asm("mov.b64 {%0,%1},%2;" : "=f"(x), "=f"(y) : "l"(v));
}
__device__ __forceinline__ u64 bc2(float x) { return pk2(x, x); }
__device__ __forceinline__ u64 swap2(u64 v) {
    float x, y; upk2(v, x, y); return pk2(y, x);
}
__device__ __forceinline__ u64 f2mul(u64 a, u64 b) {
    u64 r; asm("mul.rn.f32x2 %0,%1,%2;" : "=l"(r) : "l"(a), "l"(b)); return r;
}
__device__ __forceinline__ u64 f2fma(u64 a, u64 b, u64 c) {
    u64 r; asm("fma.rn.f32x2 %0,%1,%2,%3;" : "=l"(r) : "l"(a), "l"(b), "l"(c)); return r;
}
__device__ __forceinline__ u64 shfl2x(u64 v, int m) {
    float x, y; upk2(v, x, y);
    x = __shfl_xor_sync(0xffffffffu, x, m);
    y = __shfl_xor_sync(0xffffffffu, y, m);
    return pk2(x, y);
}
__device__ __forceinline__ void ld_h2(const __half2* p, float& re, float& im) {
    float2 v = __half22float2(*p); re = v.x; im = v.y;
}
__device__ __forceinline__ void st_h2(__half2* p, float re, float im) {
    *p = __floats2half2_rn(re, im);
}
__device__ __forceinline__ float2 cmulf(float2 a, float2 b) {
    return make_float2(a.x * b.x - a.y * b.y, a.x * b.y + a.y * b.x);
}
__device__ __forceinline__ int sfx5(int v) {
    v ^= v >> 1; v ^= v >> 2; v ^= v >> 4; return v & 31;
}

// U = Ry(p2)*Rx(p1)*Rz(p0): u00r,u00i,u01r,u01i,u10r,u10i,u11r,u11i
__device__ __forceinline__ void compute_gate(const float* __restrict__ par,
                                             int layer, int cq, float* uo) {
    const float* pp = par + ((layer * 16 + cq) * 3);
    float sz, cz, sx, cx_, sy, cy;
    sincosf(0.5f * pp[0], &sz, &cz);
    sincosf(0.5f * pp[1], &sx, &cx_);
    sincosf(0.5f * pp[2], &sy, &cy);
    float M00r =  cx_ * cz, M00i = -cx_ * sz;
    float M01r =  sx  * sz, M01i = -sx  * cz;
    float M10r = -sx  * sz, M10i = -sx  * cz;
    float M11r =  cx_ * cz, M11i =  cx_ * sz;
    uo[0] = cy * M00r - sy * M10r;  uo[1] = cy * M00i - sy * M10i;
    uo[2] = cy * M01r - sy * M11r;  uo[3] = cy * M01i - sy * M11i;
    uo[4] = sy * M00r + cy * M10r;  uo[5] = sy * M00i + cy * M10i;
    uo[6] = sy * M01r + cy * M11r;  uo[7] = sy * M01i + cy * M11i;
}

// packed gate on slot bit B, pure f32x2
template<int B>
__device__ __forceinline__ void rgateP(u64* VR, u64* VI, const float* __restrict__ u) {
    const u64 U0 = bc2(u[0]), U1 = bc2(u[1]), N1 = bc2(-u[1]);
    const u64 U2 = bc2(u[2]), U3 = bc2(u[3]), N3 = bc2(-u[3]);
    const u64 U4 = bc2(u[4]), U5 = bc2(u[5]), N5 = bc2(-u[5]);
    const u64 U6 = bc2(u[6]), U7 = bc2(u[7]), N7 = bc2(-u[7]);
    #pragma unroll
    for (int s = 0; s < 8; ++s) if (!(s & B)) {
        u64 ar = VR[s], ai = VI[s], br = VR[s | B], bi = VI[s | B];
        VR[s]     = f2fma(N3, bi, f2fma(U2, br, f2fma(N1, ai, f2mul(U0, ar))));
        VI[s]     = f2fma(U3, br, f2fma(U2, bi, f2fma(U1, ar, f2mul(U0, ai))));
        VR[s | B] = f2fma(N7, bi, f2fma(U6, br, f2fma(N5, ai, f2mul(U4, ar))));
        VI[s | B] = f2fma(U7, br, f2fma(U6, bi, f2fma(U5, ar, f2mul(U4, ai))));
    }
}

// gate on the pack bit itself — packed form:
// V=(a,b): newV = Ca (.) V + Cb (.) swap(V), Ca=(U00,U11), Cb=(U01,U10)
__device__ __forceinline__ void pgateP(u64* VR, u64* VI, const float* __restrict__ u) {
    const u64 CAR = pk2(u[0],  u[6]), CAI = pk2(u[1],  u[7]);
    const u64 NAI = pk2(-u[1], -u[7]);
    const u64 CBR = pk2(u[2],  u[4]), CBI = pk2(u[3],  u[5]);
    const u64 NBI = pk2(-u[3], -u[5]);
    #pragma unroll
    for (int s = 0; s < 8; ++s) {
        u64 wr = swap2(VR[s]), wi = swap2(VI[s]);
        u64 nr = f2fma(NBI, wi, f2fma(CBR, wr, f2fma(NAI, VI[s], f2mul(CAR, VR[s]))));
        u64 ni = f2fma(CBI, wr, f2fma(CBR, wi, f2fma(CAI, VR[s], f2mul(CAR, VI[s]))));
        VR[s] = nr; VI[s] = ni;
    }
}

// packed gate on lane bit j (shfl butterfly)
__device__ __forceinline__ void lgateP(u64* VR, u64* VI, const float* __restrict__ u,
                                       int lane, int j) {
    const int hi = (lane >> j) & 1;
    const float car = hi ? u[6] : u[0], cai = hi ? u[7] : u[1];
    const float cbr = hi ? u[4] : u[2], cbi = hi ? u[5] : u[3];
    const u64 CAR = bc2(car), CAI = bc2(cai), NAI = bc2(-cai);
    const u64 CBR = bc2(cbr), CBI = bc2(cbi), NBI = bc2(-cbi);
    #pragma unroll
    for (int s = 0; s < 8; ++s) {
        u64 pr = shfl2x(VR[s], 1 << j), pi = shfl2x(VI[s], 1 << j);
        u64 nr = f2fma(NBI, pi, f2fma(CBR, pr, f2fma(NAI, VI[s], f2mul(CAR, VR[s]))));
        u64 ni = f2fma(CBI, pr, f2fma(CBR, pi, f2fma(CAI, VR[s], f2mul(CAR, VI[s]))));
        VR[s] = nr; VI[s] = ni;
    }
}

// pass-B gates: rgate bits 5,6,7 + lgate bits 0..4 (pack = b15, never gated)
__device__ __forceinline__ void kb_gates(u64* VR, u64* VI, const float* gU, int lane) {
    rgateP<1>(VR, VI, gU + 40);
    rgateP<2>(VR, VI, gU + 48);
    rgateP<4>(VR, VI, gU + 56);
    #pragma unroll
    for (int j = 0; j < 5; ++j) lgateP(VR, VI, gU + j * 8, lane, j);
}

// pass-B store with full ladder perm folded in.
// dest low8 d = sfx8((k<<5)|lane) ^ (b8?255:0); b15' = b15 ^ d0.
__device__ __forceinline__ void kb_store(u64* VR, u64* VI, unsigned base,
                                         int cc, int w, int lane) {
    const int b8 = w & 1;
    const int S  = sfx5(lane);
    const int pl = __popc((unsigned)lane) & 1;
    #pragma unroll
    for (int k = 0; k < 8; ++k) {
        const int pk  = __popc((unsigned)k) & 1;                 // compile-time
        const int s3  = (k ^ (k >> 1) ^ (k >> 2)) & 7;           // sfx3(k), ct
        int flip = pk ^ b8;                                      // warp-uniform
        int dlo  = S ^ (flip ? 31 : 0);
        int dh3  = s3 ^ (b8 ? 7 : 0);
        int d0   = pl ^ flip;                                    // per lane
        float r0, r1, i0, i1;
        upk2(VR[k], r0, r1); upk2(VI[k], i0, i1);
        float Ar = d0 ? r1 : r0, Ai = d0 ? i1 : i0;              // dest b15'=0
        float Br = d0 ? r0 : r1, Bi = d0 ? i0 : i1;              // dest b15'=1
        unsigned a = base | (cc << 12) | (w << 8) | (dh3 << 5) | dlo;
        st_h2(&g_st[a], Ar, Ai);
        st_h2(&g_st[a | 0x8000u], Br, Bi);
    }
}

// ---------------------------------------------------------------------------
// Pass A (layers 1..3): lanes = bits 0..4, c3 = bits 5..7 (grid).
// Stage1: warp w = bits 12..15, slots = bits 8..10, pack = bit 11.
// Stage2 (after SMEM exchange): slots = bits 12..14, pack = bit 15.
// sfx8 perm on bits 8..15 folded into store address.
// ---------------------------------------------------------------------------
__global__ void __launch_bounds__(TPB, 2) kA(const float* __restrict__ par,
                                             int layer, int boff) {
    extern __shared__ float2 buf[];               // 8192 float2 = 64KB
    float* gU = (float*)(buf + 8192);             // 64 floats

    const int tid = threadIdx.x, lane = tid & 31, w = tid >> 5;
    const int c3  = blockIdx.x;
    const unsigned base = (unsigned)(blockIdx.y + boff) << 16;

    if (tid < 8) compute_gate(par, layer, 7 - tid, gU + tid * 8);  // bit 8+j -> cq 7-j

    u64 VR[8], VI[8];
    #pragma unroll
    for (int k = 0; k < 8; ++k) {
        unsigned g0 = base | (w << 12) | (k << 8) | (c3 << 5) | lane;
        float ar, ai, br, bi;
        ld_h2(&g_st[g0], ar, ai);
        ld_h2(&g_st[g0 | (8u << 8)], br, bi);
        VR[k] = pk2(ar, br); VI[k] = pk2(ai, bi);
    }
    __syncthreads();                               // gU visible

    // stage1: gates bits 8,9,10 (slots) + 11 (pack)
    rgateP<1>(VR, VI, gU + 0);
    rgateP<2>(VR, VI, gU + 8);
    rgateP<4>(VR, VI, gU + 16);
    pgateP(VR, VI, gU + 24);

    // exchange: buf[e8][e12=w][lane]
    #pragma unroll
    for (int k = 0; k < 8; ++k) {
        float r0, r1, i0, i1;
        upk2(VR[k], r0, r1); upk2(VI[k], i0, i1);
        buf[(k * 16 + w) * 32 + lane]       = make_float2(r0, i0);
        buf[((8 | k) * 16 + w) * 32 + lane] = make_float2(r1, i1);
    }
    __syncthreads();
    #pragma unroll
    for (int k = 0; k < 8; ++k) {
        float2 a = buf[(w * 16 + k) * 32 + lane];        // e8=w, e12=k
        float2 b = buf[(w * 16 + (8 | k)) * 32 + lane];  // e12=8|k
        VR[k] = pk2(a.x, b.x); VI[k] = pk2(a.y, b.y);
    }

    // stage2: gates bits 12,13,14 (slots) + 15 (pack)
    rgateP<1>(VR, VI, gU + 32);
    rgateP<2>(VR, VI, gU + 40);
    rgateP<4>(VR, VI, gU + 48);
    pgateP(VR, VI, gU + 56);

    // store with sfx8 perm on hi bits folded in
    int sw = w ^ (w >> 1); sw ^= (sw >> 2);
    const int dwA = sw, dwB = sw ^ 15;
    #pragma unroll
    for (int k = 0; k < 8; ++k) {
        float r0, r1, i0, i1;
        upk2(VR[k], r0, r1); upk2(VI[k], i0, i1);
        #pragma unroll
        for (int h = 0; h < 2; ++h) {
            int e12 = (h << 3) | k;
            int d12 = e12 ^ (e12 >> 1); d12 ^= (d12 >> 2);
            int dw  = (__popc((unsigned)e12) & 1) ? dwB : dwA;
            unsigned g = base | (d12 << 12) | (dw << 8) | (c3 << 5) | lane;
            st_h2(&g_st[g], h ? r1 : r0, h ? i1 : i0);
        }
    }
}

// ---------------------------------------------------------------------------
// kB0 (layer 0): synthesize state (product state after RX init + layer-0 hi
// gates + hi perm) from tables, then layer-0 lo gates + perm + store.
// ---------------------------------------------------------------------------
__global__ void __launch_bounds__(TPB, 2) kB0(const float* __restrict__ x,
                                              const float* __restrict__ par,
                                              int boff) {
    __shared__ float4 fv[16];      // per-qubit 2-vec factors (complex pairs)
    __shared__ float  gU[64];
    __shared__ float2 Tlo[256], Thi[256];

    const int tid = threadIdx.x, lane = tid & 31, w = tid >> 5;  // w = bits 8..11
    const int cc  = blockIdx.x;
    const int b   = blockIdx.y + boff;
    const unsigned base = (unsigned)b << 16;

    if (tid < 16) {
        int m = tid;                         // index bit m <-> cq 15-m
        float s, c; sincosf(0.5f * x[b * 16 + (15 - m)], &s, &c);
        if (m < 8) {
            fv[m] = make_float4(c, 0.f, 0.f, -s);          // RX|0> = (c, -i s)
        } else {
            float U[8]; compute_gate(par, 0, 15 - m, U);   // layer-0 hi gate
            fv[m] = make_float4(U[0]*c + U[3]*s, U[1]*c - U[2]*s,
                                U[4]*c + U[7]*s, U[5]*c - U[6]*s);
        }
    } else if (tid >= 32 && tid < 40) {
        compute_gate(par, 0, 15 - (tid - 32), gU + (tid - 32) * 8);  // lo gates
    }
    __syncthreads();

    {   // build tables: threads 0..255 -> Tlo, 256..511 -> Thi (perm-relabeled)
        int e = tid & 255;
        int mbase = (tid < 256) ? 0 : 8;
        float2 cacc = make_float2(1.f, 0.f);
        #pragma unroll
        for (int m = 0; m < 8; ++m) {
            float4 F = fv[mbase + m];
            float2 bb = ((e >> m) & 1) ? make_float2(F.z, F.w)
                                       : make_float2(F.x, F.y);
            cacc = cmulf(cacc, bb);
        }
        if (tid < 256) {
            Tlo[e] = cacc;
        } else {
            int d = e ^ (e >> 1); d ^= d >> 2; d ^= d >> 4;   // sfx8(e)
            Thi[d & 255] = cacc;                              // Thi[h]=F(inv(h))
        }
    }
    __syncthreads();

    u64 VR[8], VI[8];
    float2 H0 = Thi[w | (cc << 4)];
    float2 H1 = Thi[w | (cc << 4) | 128];
    #pragma unroll
    for (int k = 0; k < 8; ++k) {
        float2 L  = Tlo[(k << 5) | lane];
        float2 a0 = cmulf(H0, L), a1 = cmulf(H1, L);
        VR[k] = pk2(a0.x, a1.x); VI[k] = pk2(a0.y, a1.y);
    }

    kb_gates(VR, VI, gU, lane);
    kb_store(VR, VI, base, cc, w, lane);
}

// ---------------------------------------------------------------------------
// kBmid (layers 1,2): load, lo gates, perm-folded store.
// ---------------------------------------------------------------------------
__global__ void __launch_bounds__(TPB, 2) kBmid(const float* __restrict__ par,
                                                int layer, int boff) {
    __shared__ float gU[64];

    const int tid = threadIdx.x, lane = tid & 31, w = tid >> 5;
    const int cc  = blockIdx.x;
    const unsigned base = (unsigned)(blockIdx.y + boff) << 16;

    if (tid < 8) compute_gate(par, layer, 15 - tid, gU + tid * 8);

    u64 VR[8], VI[8];
    #pragma unroll
    for (int k = 0; k < 8; ++k) {
        unsigned a = base | (cc << 12) | (w << 8) | (k << 5) | lane;
        float r0, i0, r1, i1;
        ld_h2(&g_st[a], r0, i0);
        ld_h2(&g_st[a | 0x8000u], r1, i1);
        VR[k] = pk2(r0, r1); VI[k] = pk2(i0, i1);
    }
    __syncthreads();

    kb_gates(VR, VI, gU, lane);
    kb_store(VR, VI, base, cc, w, lane);
}

// ---------------------------------------------------------------------------
// kBlast (layer 3): lo gates, then <Z> partials with perm folded analytically.
// ---------------------------------------------------------------------------
__global__ void __launch_bounds__(TPB, 2) kBlast(const float* __restrict__ par,
                                                 int layer, int boff) {
    __shared__ float gU[64];
    __shared__ float red[16][17];

    const int tid = threadIdx.x, lane = tid & 31, w = tid >> 5;
    const int cc  = blockIdx.x;
    const int b   = blockIdx.y + boff;
    const unsigned base = (unsigned)b << 16;
    const int b8 = w & 1;

    if (tid < 8) compute_gate(par, layer, 15 - tid, gU + tid * 8);

    u64 VR[8], VI[8];
    #pragma unroll
    for (int k = 0; k < 8; ++k) {
        unsigned a = base | (cc << 12) | (w << 8) | (k << 5) | lane;
        float r0, i0, r1, i1;
        ld_h2(&g_st[a], r0, i0);
        ld_h2(&g_st[a | 0x8000u], r1, i1);
        VR[k] = pk2(r0, r1); VI[k] = pk2(i0, i1);
    }
    __syncthreads();

    kb_gates(VR, VI, gU, lane);

    // probabilities; ee indexed by j0 = sfx3(k) (ct); W0 with (-1)^par(k)
    float ee[8], W0 = 0.f;
    #pragma unroll
    for (int k = 0; k < 8; ++k) {
        const int j0 = (k ^ (k >> 1) ^ (k >> 2)) & 7;
        const int pk = __popc((unsigned)k) & 1;
        float r0, r1, i0, i1;
        upk2(VR[k], r0, r1); upk2(VI[k], i0, i1);
        float p0 = r0 * r0 + i0 * i0, p1 = r1 * r1 + i1 * i1;
        ee[j0] = p0 + p1;
        W0 += pk ? (p1 - p0) : (p0 - p1);
    }
    // Walsh tree over ee (dest bits 5..7, pre b8-relabel)
    float e04 = ee[0] + ee[4], e15 = ee[1] + ee[5];
    float e26 = ee[2] + ee[6], e37 = ee[3] + ee[7];
    float T7 = (ee[0] - ee[4]) + (ee[1] - ee[5]) + (ee[2] - ee[6]) + (ee[3] - ee[7]);
    float a0 = e04 + e26, a1 = e15 + e37;
    float T6 = (e04 - e26) + (e15 - e37);
    float T0 = a0 + a1, T5 = a0 - a1;
    if (b8) { T5 = -T5; T6 = -T6; T7 = -T7; W0 = -W0; }  // j -> j^7, sign flip

    const int S  = sfx5(lane);
    const int pl = __popc((unsigned)lane) & 1;
    float acc[16];
    #pragma unroll
    for (int m = 0; m < 16; ++m) {
        if      (m < 5)   acc[m] = ((S >> m) & 1) ? -T5 : T5;
        else if (m == 5)  acc[m] = T5;
        else if (m == 6)  acc[m] = T6;
        else if (m == 7)  acc[m] = T7;
        else if (m < 12)  acc[m] = ((w >> (m - 8)) & 1) ? -T0 : T0;
        else if (m < 15)  acc[m] = ((cc >> (m - 12)) & 1) ? -T0 : T0;
        else              acc[m] = pl ? -W0 : W0;
    }

    #pragma unroll
    for (int m = 0; m < 16; ++m) {
        float v = acc[m];
        #pragma unroll
        for (int o = 16; o > 0; o >>= 1) v += __shfl_xor_sync(0xffffffffu, v, o);
        if (lane == 0) red[m][w] = v;
    }
    __syncthreads();
    if (tid < 16) {
        float s = 0.f;
        #pragma unroll
        for (int k = 0; k < 16; ++k) s += red[tid][k];
        g_part[(b * 8 + cc) * 16 + tid] = s;
    }
}

__global__ void kBfin(float* __restrict__ out) {
    int i = blockIdx.x * blockDim.x + threadIdx.x;
    if (i < BAT * 16) {
        int b = i >> 4, m = i & 15;
        float s = 0.f;
        #pragma unroll
        for (int cc = 0; cc < 8; ++cc) s += g_part[(b * 8 + cc) * 16 + m];
        out[b * 16 + (15 - m)] = s;
    }
}

// ---------------------------------------------------------------------------
extern "C" void kernel_launch(void* const* d_in, const int* in_sizes, int n_in,
                              void* d_out, int out_size) {
    const float* x   = (const float*)d_in[0];
    const float* par = (const float*)d_in[1];
    if (n_in >= 2 && in_sizes[0] == 192) {
        const float* t = x; x = par; par = t;
    }
    float* out = (float*)d_out;

    const size_t smA = 8192 * sizeof(float2) + 64 * sizeof(float);
    cudaFuncSetAttribute(kA, cudaFuncAttributeMaxDynamicSharedMemorySize, (int)smA);

    dim3 grid(8, CHUNK);
    for (int boff = 0; boff < BAT; boff += CHUNK) {
        kB0<<<grid, TPB>>>(x, par, boff);                 // layer 0
        for (int layer = 1; layer < 4; ++layer) {
            kA<<<grid, TPB, smA>>>(par, layer, boff);
            if (layer < 3) kBmid<<<grid, TPB>>>(par, layer, boff);
            else           kBlast<<<grid, TPB>>>(par, layer, boff);
        }
    }
    kBfin<<<32, 256>>>(out);
}

// round 8
// speedup vs baseline: 1.0656x; 1.0656x over previous
#include <cuda_runtime.h>
#include <cuda_fp16.h>
#include <math.h>

// ---------------------------------------------------------------------------
// 16-qubit statevector, batch 512. circuit qubit i <-> index bit (15-i).
// Layer = 16 one-qubit gates + CNOT-ladder = suffix-XOR permutation.
// State between passes: __half2(re,im), fp32 compute (f32x2 packed FMA).
// Layer 0 pass A is ANALYTIC (product state synthesized in kB0 from tables).
// Pass A (layers 1..3): gates bits 8..15, two rgate stages + SMEM exchange,
//   hi perm folded into store address.
// Pass B: lane = bits 0..4, slots k = bits 5..7, pack = b15 (ungated),
//   warp w = bits 8..11. Ladder perm on bits 0..7 + b15-wrap folded into
//   store: dense 128B blocks, pack halves swapped by dest bit 0.
// ---------------------------------------------------------------------------

#define TPB 512
#define BAT 512

typedef unsigned long long u64;

__device__ __half2 g_st[(size_t)BAT * 65536];
__device__ float   g_part[BAT * 8 * 16];

// ---------------- packed f32x2 helpers ----------------
__device__ __forceinline__ u64 pk2(float x, float y) {
    u64 r; asm("mov.b64 %0,{%1,%2};" : "=l"(r) : "f"(x), "f"(y)); return r;
}
__device__ __forceinline__ void upk2(u64 v, float& x, float& y) {
    asm("mov.b64 {%0,%1},%2;" : "=f"(x), "=f"(y) : "l"(v));
}
__device__ __forceinline__ u64 bc2(float x) { return pk2(x, x); }
__device__ __forceinline__ u64 f2mul(u64 a, u64 b) {
    u64 r; asm("mul.rn.f32x2 %0,%1,%2;" : "=l"(r) : "l"(a), "l"(b)); return r;
}
__device__ __forceinline__ u64 f2fma(u64 a, u64 b, u64 c) {
    u64 r; asm("fma.rn.f32x2 %0,%1,%2,%3;" : "=l"(r) : "l"(a), "l"(b), "l"(c)); return r;
}
// native 64-bit shuffle: no manual pack/unpack MOVs
__device__ __forceinline__ u64 shfl2x(u64 v, int m) {
    return __shfl_xor_sync(0xffffffffu, v, m);
}
__device__ __forceinline__ void ld_h2(const __half2* p, float& re, float& im) {
    float2 v = __half22float2(__ldg(p)); re = v.x; im = v.y;
}
__device__ __forceinline__ void st_h2(__half2* p, float re, float im) {
    *p = __floats2half2_rn(re, im);
}
__device__ __forceinline__ float2 cmulf(float2 a, float2 b) {
    return make_float2(a.x * b.x - a.y * b.y, a.x * b.y + a.y * b.x);
}
__device__ __forceinline__ int sfx5(int v) {
    v ^= v >> 1; v ^= v >> 2; v ^= v >> 4; return v & 31;
}

// U = Ry(p2)*Rx(p1)*Rz(p0): u00r,u00i,u01r,u01i,u10r,u10i,u11r,u11i
__device__ __forceinline__ void compute_gate(const float* __restrict__ par,
                                             int layer, int cq, float* uo) {
    const float* pp = par + ((layer * 16 + cq) * 3);
    float sz, cz, sx, cx_, sy, cy;
    sincosf(0.5f * pp[0], &sz, &cz);
    sincosf(0.5f * pp[1], &sx, &cx_);
    sincosf(0.5f * pp[2], &sy, &cy);
    float M00r =  cx_ * cz, M00i = -cx_ * sz;
    float M01r =  sx  * sz, M01i = -sx  * cz;
    float M10r = -sx  * sz, M10i = -sx  * cz;
    float M11r =  cx_ * cz, M11i =  cx_ * sz;
    uo[0] = cy * M00r - sy * M10r;  uo[1] = cy * M00i - sy * M10i;
    uo[2] = cy * M01r - sy * M11r;  uo[3] = cy * M01i - sy * M11i;
    uo[4] = sy * M00r + cy * M10r;  uo[5] = sy * M00i + cy * M10i;
    uo[6] = sy * M01r + cy * M11r;  uo[7] = sy * M01i + cy * M11i;
}

// packed gate on slot bit B, pure f32x2
template<int B>
__device__ __forceinline__ void rgateP(u64* VR, u64* VI, const float* __restrict__ u) {
    const u64 U0 = bc2(u[0]), U1 = bc2(u[1]), N1 = bc2(-u[1]);
    const u64 U2 = bc2(u[2]), U3 = bc2(u[3]), N3 = bc2(-u[3]);
    const u64 U4 = bc2(u[4]), U5 = bc2(u[5]), N5 = bc2(-u[5]);
    const u64 U6 = bc2(u[6]), U7 = bc2(u[7]), N7 = bc2(-u[7]);
    #pragma unroll
    for (int s = 0; s < 8; ++s) if (!(s & B)) {
        u64 ar = VR[s], ai = VI[s], br = VR[s | B], bi = VI[s | B];
        VR[s]     = f2fma(N3, bi, f2fma(U2, br, f2fma(N1, ai, f2mul(U0, ar))));
        VI[s]     = f2fma(U3, br, f2fma(U2, bi, f2fma(U1, ar, f2mul(U0, ai))));
        VR[s | B] = f2fma(N7, bi, f2fma(U6, br, f2fma(N5, ai, f2mul(U4, ar))));
        VI[s | B] = f2fma(U7, br, f2fma(U6, bi, f2fma(U5, ar, f2mul(U4, ai))));
    }
}

// gate on the pack bit itself (pairs = the two halves of each pack), scalar FFMA
__device__ __forceinline__ void pgateP(u64* VR, u64* VI, const float* __restrict__ u) {
    #pragma unroll
    for (int s = 0; s < 8; ++s) {
        float ar, br, ai, bi;
        upk2(VR[s], ar, br); upk2(VI[s], ai, bi);
        float nar = u[0]*ar - u[1]*ai + u[2]*br - u[3]*bi;
        float nai = u[0]*ai + u[1]*ar + u[2]*bi + u[3]*br;
        float nbr = u[4]*ar - u[5]*ai + u[6]*br - u[7]*bi;
        float nbi = u[4]*ai + u[5]*ar + u[6]*bi + u[7]*br;
        VR[s] = pk2(nar, nbr); VI[s] = pk2(nai, nbi);
    }
}

// packed gate on lane bit j (shfl butterfly)
__device__ __forceinline__ void lgateP(u64* VR, u64* VI, const float* __restrict__ u,
                                       int lane, int j) {
    const int hi = (lane >> j) & 1;
    const float car = hi ? u[6] : u[0], cai = hi ? u[7] : u[1];
    const float cbr = hi ? u[4] : u[2], cbi = hi ? u[5] : u[3];
    const u64 CAR = bc2(car), CAI = bc2(cai), NAI = bc2(-cai);
    const u64 CBR = bc2(cbr), CBI = bc2(cbi), NBI = bc2(-cbi);
    #pragma unroll
    for (int s = 0; s < 8; ++s) {
        u64 pr = shfl2x(VR[s], 1 << j), pi = shfl2x(VI[s], 1 << j);
        u64 nr = f2fma(NBI, pi, f2fma(CBR, pr, f2fma(NAI, VI[s], f2mul(CAR, VR[s]))));
        u64 ni = f2fma(CBI, pr, f2fma(CBR, pi, f2fma(CAI, VR[s], f2mul(CAR, VI[s]))));
        VR[s] = nr; VI[s] = ni;
    }
}

// pass-B gates: rgate bits 5,6,7 + lgate bits 0..4 (pack = b15, never gated)
__device__ __forceinline__ void kb_gates(u64* VR, u64* VI, const float* gU, int lane) {
    rgateP<1>(VR, VI, gU + 40);
    rgateP<2>(VR, VI, gU + 48);
    rgateP<4>(VR, VI, gU + 56);
    #pragma unroll
    for (int j = 0; j < 5; ++j) lgateP(VR, VI, gU + j * 8, lane, j);
}

// pass-B store with full ladder perm folded in.
// dest low8 d = sfx8((k<<5)|lane) ^ (b8?255:0); b15' = b15 ^ d0.
__device__ __forceinline__ void kb_store(u64* VR, u64* VI, unsigned base,
                                         int cc, int w, int lane) {
    const int b8 = w & 1;
    const int S  = sfx5(lane);
    const int pl = __popc((unsigned)lane) & 1;
    #pragma unroll
    for (int k = 0; k < 8; ++k) {
        const int pk  = __popc((unsigned)k) & 1;                 // compile-time
        const int s3  = (k ^ (k >> 1) ^ (k >> 2)) & 7;           // sfx3(k), ct
        int flip = pk ^ b8;                                      // warp-uniform
        int dlo  = S ^ (flip ? 31 : 0);
        int dh3  = s3 ^ (b8 ? 7 : 0);
        int d0   = pl ^ flip;                                    // per lane
        float r0, r1, i0, i1;
        upk2(VR[k], r0, r1); upk2(VI[k], i0, i1);
        float Ar = d0 ? r1 : r0, Ai = d0 ? i1 : i0;              // dest b15'=0
        float Br = d0 ? r0 : r1, Bi = d0 ? i0 : i1;              // dest b15'=1
        unsigned a = base | (cc << 12) | (w << 8) | (dh3 << 5) | dlo;
        st_h2(&g_st[a], Ar, Ai);
        st_h2(&g_st[a | 0x8000u], Br, Bi);
    }
}

// ---------------------------------------------------------------------------
// Pass A (layers 1..3): lanes = bits 0..4, c3 = bits 5..7 (grid).
// Stage1: warp w = bits 12..15, slots = bits 8..10, pack = bit 11.
// Stage2 (after SMEM exchange): slots = bits 12..14, pack = bit 15.
// sfx8 perm on bits 8..15 folded into store address.
// ---------------------------------------------------------------------------
__global__ void __launch_bounds__(TPB, 2) kA(const float* __restrict__ par, int layer) {
    extern __shared__ float2 buf[];               // 8192 float2 = 64KB
    float* gU = (float*)(buf + 8192);             // 64 floats

    const int tid = threadIdx.x, lane = tid & 31, w = tid >> 5;
    const int c3  = blockIdx.x;
    const unsigned base = (unsigned)blockIdx.y << 16;

    if (tid < 8) compute_gate(par, layer, 7 - tid, gU + tid * 8);  // bit 8+j -> cq 7-j

    u64 VR[8], VI[8];
    #pragma unroll
    for (int k = 0; k < 8; ++k) {
        unsigned g0 = base | (w << 12) | (k << 8) | (c3 << 5) | lane;
        float ar, ai, br, bi;
        ld_h2(&g_st[g0], ar, ai);
        ld_h2(&g_st[g0 | (8u << 8)], br, bi);
        VR[k] = pk2(ar, br); VI[k] = pk2(ai, bi);
    }
    __syncthreads();                               // gU visible

    // stage1: gates bits 8,9,10 (slots) + 11 (pack)
    rgateP<1>(VR, VI, gU + 0);
    rgateP<2>(VR, VI, gU + 8);
    rgateP<4>(VR, VI, gU + 16);
    pgateP(VR, VI, gU + 24);

    // exchange: buf[e8][e12=w][lane]
    #pragma unroll
    for (int k = 0; k < 8; ++k) {
        float r0, r1, i0, i1;
        upk2(VR[k], r0, r1); upk2(VI[k], i0, i1);
        buf[(k * 16 + w) * 32 + lane]       = make_float2(r0, i0);
        buf[((8 | k) * 16 + w) * 32 + lane] = make_float2(r1, i1);
    }
    __syncthreads();
    #pragma unroll
    for (int k = 0; k < 8; ++k) {
        float2 a = buf[(w * 16 + k) * 32 + lane];        // e8=w, e12=k
        float2 b = buf[(w * 16 + (8 | k)) * 32 + lane];  // e12=8|k
        VR[k] = pk2(a.x, b.x); VI[k] = pk2(a.y, b.y);
    }

    // stage2: gates bits 12,13,14 (slots) + 15 (pack)
    rgateP<1>(VR, VI, gU + 32);
    rgateP<2>(VR, VI, gU + 40);
    rgateP<4>(VR, VI, gU + 48);
    pgateP(VR, VI, gU + 56);

    // store with sfx8 perm on hi bits folded in; h=1 address = h=0 addr ^ 0xFF00
    int sw = w ^ (w >> 1); sw ^= (sw >> 2);
    #pragma unroll
    for (int k = 0; k < 8; ++k) {
        const int d12 = ((k ^ (k >> 1)) ^ ((k ^ (k >> 1)) >> 2)) & 15;  // sfx4(k), ct
        const int pk  = __popc((unsigned)k) & 1;                        // ct
        int dw = sw ^ (pk ? 15 : 0);
        unsigned g0 = base | (d12 << 12) | (dw << 8) | (c3 << 5) | lane;
        float r0, r1, i0, i1;
        upk2(VR[k], r0, r1); upk2(VI[k], i0, i1);
        st_h2(&g_st[g0],           r0, i0);       // h=0
        st_h2(&g_st[g0 ^ 0xFF00u], r1, i1);       // h=1: d12^15, dw^15
    }
}

// ---------------------------------------------------------------------------
// kB0 (layer 0): synthesize state (product state after RX init + layer-0 hi
// gates + hi perm) from tables, then layer-0 lo gates + perm + store.
// ---------------------------------------------------------------------------
__global__ void __launch_bounds__(TPB, 2) kB0(const float* __restrict__ x,
                                              const float* __restrict__ par) {
    __shared__ float4 fv[16];      // per-qubit 2-vec factors (complex pairs)
    __shared__ float  gU[64];
    __shared__ float2 Tlo[256], Thi[256];

    const int tid = threadIdx.x, lane = tid & 31, w = tid >> 5;  // w = bits 8..11
    const int cc  = blockIdx.x;
    const unsigned base = (unsigned)blockIdx.y << 16;

    if (tid < 16) {
        int m = tid;                         // index bit m <-> cq 15-m
        float s, c; sincosf(0.5f * x[blockIdx.y * 16 + (15 - m)], &s, &c);
        if (m < 8) {
            fv[m] = make_float4(c, 0.f, 0.f, -s);          // RX|0> = (c, -i s)
        } else {
            float U[8]; compute_gate(par, 0, 15 - m, U);   // layer-0 hi gate
            fv[m] = make_float4(U[0]*c + U[3]*s, U[1]*c - U[2]*s,
                                U[4]*c + U[7]*s, U[5]*c - U[6]*s);
        }
    } else if (tid >= 32 && tid < 40) {
        compute_gate(par, 0, 15 - (tid - 32), gU + (tid - 32) * 8);  // lo gates
    }
    __syncthreads();

    {   // build tables: threads 0..255 -> Tlo, 256..511 -> Thi (perm-relabeled)
        int e = tid & 255;
        int mbase = (tid < 256) ? 0 : 8;
        float2 cacc = make_float2(1.f, 0.f);
        #pragma unroll
        for (int m = 0; m < 8; ++m) {
            float4 F = fv[mbase + m];
            float2 bb = ((e >> m) & 1) ? make_float2(F.z, F.w)
                                       : make_float2(F.x, F.y);
            cacc = cmulf(cacc, bb);
        }
        if (tid < 256) {
            Tlo[e] = cacc;
        } else {
            int d = e ^ (e >> 1); d ^= d >> 2; d ^= d >> 4;   // sfx8(e)
            Thi[d & 255] = cacc;                              // Thi[h]=F(inv(h))
        }
    }
    __syncthreads();

    u64 VR[8], VI[8];
    float2 H0 = Thi[w | (cc << 4)];
    float2 H1 = Thi[w | (cc << 4) | 128];
    #pragma unroll
    for (int k = 0; k < 8; ++k) {
        float2 L  = Tlo[(k << 5) | lane];
        float2 a0 = cmulf(H0, L), a1 = cmulf(H1, L);
        VR[k] = pk2(a0.x, a1.x); VI[k] = pk2(a0.y, a1.y);
    }

    kb_gates(VR, VI, gU, lane);
    kb_store(VR, VI, base, cc, w, lane);
}

// ---------------------------------------------------------------------------
// kBmid (layers 1,2): load, lo gates, perm-folded store.
// ---------------------------------------------------------------------------
__global__ void __launch_bounds__(TPB, 2) kBmid(const float* __restrict__ par, int layer) {
    __shared__ float gU[64];

    const int tid = threadIdx.x, lane = tid & 31, w = tid >> 5;
    const int cc  = blockIdx.x;
    const unsigned base = (unsigned)blockIdx.y << 16;

    if (tid < 8) compute_gate(par, layer, 15 - tid, gU + tid * 8);

    u64 VR[8], VI[8];
    #pragma unroll
    for (int k = 0; k < 8; ++k) {
        unsigned a = base | (cc << 12) | (w << 8) | (k << 5) | lane;
        float r0, i0, r1, i1;
        ld_h2(&g_st[a], r0, i0);
        ld_h2(&g_st[a | 0x8000u], r1, i1);
        VR[k] = pk2(r0, r1); VI[k] = pk2(i0, i1);
    }
    __syncthreads();

    kb_gates(VR, VI, gU, lane);
    kb_store(VR, VI, base, cc, w, lane);
}

// ---------------------------------------------------------------------------
// kBlast (layer 3): lo gates, then <Z> partials with perm folded analytically.
// ---------------------------------------------------------------------------
__global__ void __launch_bounds__(TPB, 2) kBlast(const float* __restrict__ par, int layer) {
    __shared__ float gU[64];
    __shared__ float red[16][17];

    const int tid = threadIdx.x, lane = tid & 31, w = tid >> 5;
    const int cc  = blockIdx.x;
    const unsigned base = (unsigned)blockIdx.y << 16;
    const int b8 = w & 1;

    if (tid < 8) compute_gate(par, layer, 15 - tid, gU + tid * 8);

    u64 VR[8], VI[8];
    #pragma unroll
    for (int k = 0; k < 8; ++k) {
        unsigned a = base | (cc << 12) | (w << 8) | (k << 5) | lane;
        float r0, i0, r1, i1;
        ld_h2(&g_st[a], r0, i0);
        ld_h2(&g_st[a | 0x8000u], r1, i1);
        VR[k] = pk2(r0, r1); VI[k] = pk2(i0, i1);
    }
    __syncthreads();

    kb_gates(VR, VI, gU, lane);

    // probabilities; ee indexed by j0 = sfx3(k) (ct); W0 with (-1)^par(k)
    float ee[8], W0 = 0.f;
    #pragma unroll
    for (int k = 0; k < 8; ++k) {
        const int j0 = (k ^ (k >> 1) ^ (k >> 2)) & 7;
        const int pk = __popc((unsigned)k) & 1;
        float r0, r1, i0, i1;
        upk2(VR[k], r0, r1); upk2(VI[k], i0, i1);
        float p0 = r0 * r0 + i0 * i0, p1 = r1 * r1 + i1 * i1;
        ee[j0] = p0 + p1;
        W0 += pk ? (p1 - p0) : (p0 - p1);
    }
    // Walsh tree over ee (dest bits 5..7, pre b8-relabel)
    float e04 = ee[0] + ee[4], e15 = ee[1] + ee[5];
    float e26 = ee[2] + ee[6], e37 = ee[3] + ee[7];
    float T7 = (ee[0] - ee[4]) + (ee[1] - ee[5]) + (ee[2] - ee[6]) + (ee[3] - ee[7]);
    float a0 = e04 + e26, a1 = e15 + e37;
    float T6 = (e04 - e26) + (e15 - e37);
    float T0 = a0 + a1, T5 = a0 - a1;
    if (b8) { T5 = -T5; T6 = -T6; T7 = -T7; W0 = -W0; }  // j -> j^7, sign flip

    const int S  = sfx5(lane);
    const int pl = __popc((unsigned)lane) & 1;
    float acc[16];
    #pragma unroll
    for (int m = 0; m < 16; ++m) {
        if      (m < 5)   acc[m] = ((S >> m) & 1) ? -T5 : T5;
        else if (m == 5)  acc[m] = T5;
        else if (m == 6)  acc[m] = T6;
        else if (m == 7)  acc[m] = T7;
        else if (m < 12)  acc[m] = ((w >> (m - 8)) & 1) ? -T0 : T0;
        else if (m < 15)  acc[m] = ((cc >> (m - 12)) & 1) ? -T0 : T0;
        else              acc[m] = pl ? -W0 : W0;
    }

    #pragma unroll
    for (int m = 0; m < 16; ++m) {
        float v = acc[m];
        #pragma unroll
        for (int o = 16; o > 0; o >>= 1) v += __shfl_xor_sync(0xffffffffu, v, o);
        if (lane == 0) red[m][w] = v;
    }
    __syncthreads();
    if (tid < 16) {
        float s = 0.f;
        #pragma unroll
        for (int k = 0; k < 16; ++k) s += red[tid][k];
        g_part[(blockIdx.y * 8 + cc) * 16 + tid] = s;
    }
}

__global__ void kBfin(float* __restrict__ out) {
    int i = blockIdx.x * blockDim.x + threadIdx.x;
    if (i < BAT * 16) {
        int b = i >> 4, m = i & 15;
        float s = 0.f;
        #pragma unroll
        for (int cc = 0; cc < 8; ++cc) s += g_part[(b * 8 + cc) * 16 + m];
        out[b * 16 + (15 - m)] = s;
    }
}

// ---------------------------------------------------------------------------
extern "C" void kernel_launch(void* const* d_in, const int* in_sizes, int n_in,
                              void* d_out, int out_size) {
    const float* x   = (const float*)d_in[0];
    const float* par = (const float*)d_in[1];
    if (n_in >= 2 && in_sizes[0] == 192) {
        const float* t = x; x = par; par = t;
    }
    float* out = (float*)d_out;

    const size_t smA = 8192 * sizeof(float2) + 64 * sizeof(float);
    cudaFuncSetAttribute(kA, cudaFuncAttributeMaxDynamicSharedMemorySize, (int)smA);

    dim3 grid8(8, BAT);
    kB0<<<grid8, TPB>>>(x, par);                       // layer 0 (A analytic + B)
    for (int layer = 1; layer < 4; ++layer) {
        kA<<<grid8, TPB, smA>>>(par, layer);
        if (layer < 3) {
            kBmid<<<grid8, TPB>>>(par, layer);
        } else {
            kBlast<<<grid8, TPB>>>(par, layer);
            kBfin<<<32, 256>>>(out);
        }
    }
}

// round 9
// speedup vs baseline: 1.0918x; 1.0246x over previous
#include <cuda_runtime.h>
#include <cuda_fp16.h>
#include <math.h>

// ---------------------------------------------------------------------------
// 16-qubit statevector, batch 512. circuit qubit i <-> index bit (15-i).
// Layer = 16 one-qubit gates + CNOT-ladder = suffix-XOR permutation.
// State between passes: __half2(re,im), fp32 compute (f32x2 packed FMA).
// Layer 0 pass A is ANALYTIC (product state synthesized in kB0 from tables).
// kA / kBmid / kBlast are PERSISTENT (grid = 2 x #SM, grid-stride over the
// 4096 (batch, chunk) tiles): gate table computed once per CTA, loop
// barrier-free in the B kernels.
// ---------------------------------------------------------------------------

#define TPB 512
#define BAT 512
#define NTILES 4096

typedef unsigned long long u64;

__device__ __half2 g_st[(size_t)BAT * 65536];
__device__ float   g_part[BAT * 8 * 16];

// ---------------- packed f32x2 helpers ----------------
__device__ __forceinline__ u64 pk2(float x, float y) {
    u64 r; asm("mov.b64 %0,{%1,%2};" : "=l"(r) : "f"(x), "f"(y)); return r;
}
__device__ __forceinline__ void upk2(u64 v, float& x, float& y) {
    asm("mov.b64 {%0,%1},%2;" : "=f"(x), "=f"(y) : "l"(v));
}
__device__ __forceinline__ u64 bc2(float x) { return pk2(x, x); }
__device__ __forceinline__ u64 f2mul(u64 a, u64 b) {
    u64 r; asm("mul.rn.f32x2 %0,%1,%2;" : "=l"(r) : "l"(a), "l"(b)); return r;
}
__device__ __forceinline__ u64 f2fma(u64 a, u64 b, u64 c) {
    u64 r; asm("fma.rn.f32x2 %0,%1,%2,%3;" : "=l"(r) : "l"(a), "l"(b), "l"(c)); return r;
}
__device__ __forceinline__ u64 shfl2x(u64 v, int m) {
    float x, y; upk2(v, x, y);
    x = __shfl_xor_sync(0xffffffffu, x, m);
    y = __shfl_xor_sync(0xffffffffu, y, m);
    return pk2(x, y);
}
__device__ __forceinline__ void ld_h2(const __half2* p, float& re, float& im) {
    float2 v = __half22float2(*p); re = v.x; im = v.y;
}
__device__ __forceinline__ void st_h2(__half2* p, float re, float im) {
    *p = __floats2half2_rn(re, im);
}
__device__ __forceinline__ float2 cmulf(float2 a, float2 b) {
    return make_float2(a.x * b.x - a.y * b.y, a.x * b.y + a.y * b.x);
}
__device__ __forceinline__ int sfx5(int v) {
    v ^= v >> 1; v ^= v >> 2; v ^= v >> 4; return v & 31;
}

// U = Ry(p2)*Rx(p1)*Rz(p0): u00r,u00i,u01r,u01i,u10r,u10i,u11r,u11i
__device__ __forceinline__ void compute_gate(const float* __restrict__ par,
                                             int layer, int cq, float* uo) {
    const float* pp = par + ((layer * 16 + cq) * 3);
    float sz, cz, sx, cx_, sy, cy;
    sincosf(0.5f * pp[0], &sz, &cz);
    sincosf(0.5f * pp[1], &sx, &cx_);
    sincosf(0.5f * pp[2], &sy, &cy);
    float M00r =  cx_ * cz, M00i = -cx_ * sz;
    float M01r =  sx  * sz, M01i = -sx  * cz;
    float M10r = -sx  * sz, M10i = -sx  * cz;
    float M11r =  cx_ * cz, M11i =  cx_ * sz;
    uo[0] = cy * M00r - sy * M10r;  uo[1] = cy * M00i - sy * M10i;
    uo[2] = cy * M01r - sy * M11r;  uo[3] = cy * M01i - sy * M11i;
    uo[4] = sy * M00r + cy * M10r;  uo[5] = sy * M00i + cy * M10i;
    uo[6] = sy * M01r + cy * M11r;  uo[7] = sy * M01i + cy * M11i;
}

// packed gate on slot bit B, pure f32x2
template<int B>
__device__ __forceinline__ void rgateP(u64* VR, u64* VI, const float* __restrict__ u) {
    const u64 U0 = bc2(u[0]), U1 = bc2(u[1]), N1 = bc2(-u[1]);
    const u64 U2 = bc2(u[2]), U3 = bc2(u[3]), N3 = bc2(-u[3]);
    const u64 U4 = bc2(u[4]), U5 = bc2(u[5]), N5 = bc2(-u[5]);
    const u64 U6 = bc2(u[6]), U7 = bc2(u[7]), N7 = bc2(-u[7]);
    #pragma unroll
    for (int s = 0; s < 8; ++s) if (!(s & B)) {
        u64 ar = VR[s], ai = VI[s], br = VR[s | B], bi = VI[s | B];
        VR[s]     = f2fma(N3, bi, f2fma(U2, br, f2fma(N1, ai, f2mul(U0, ar))));
        VI[s]     = f2fma(U3, br, f2fma(U2, bi, f2fma(U1, ar, f2mul(U0, ai))));
        VR[s | B] = f2fma(N7, bi, f2fma(U6, br, f2fma(N5, ai, f2mul(U4, ar))));
        VI[s | B] = f2fma(U7, br, f2fma(U6, bi, f2fma(U5, ar, f2mul(U4, ai))));
    }
}

// gate on the pack bit itself (pairs = the two halves of each pack), scalar FFMA
__device__ __forceinline__ void pgateP(u64* VR, u64* VI, const float* __restrict__ u) {
    #pragma unroll
    for (int s = 0; s < 8; ++s) {
        float ar, br, ai, bi;
        upk2(VR[s], ar, br); upk2(VI[s], ai, bi);
        float nar = u[0]*ar - u[1]*ai + u[2]*br - u[3]*bi;
        float nai = u[0]*ai + u[1]*ar + u[2]*bi + u[3]*br;
        float nbr = u[4]*ar - u[5]*ai + u[6]*br - u[7]*bi;
        float nbi = u[4]*ai + u[5]*ar + u[6]*bi + u[7]*br;
        VR[s] = pk2(nar, nbr); VI[s] = pk2(nai, nbi);
    }
}

// packed gate on lane bit j (shfl butterfly)
__device__ __forceinline__ void lgateP(u64* VR, u64* VI, const float* __restrict__ u,
                                       int lane, int j) {
    const int hi = (lane >> j) & 1;
    const float car = hi ? u[6] : u[0], cai = hi ? u[7] : u[1];
    const float cbr = hi ? u[4] : u[2], cbi = hi ? u[5] : u[3];
    const u64 CAR = bc2(car), CAI = bc2(cai), NAI = bc2(-cai);
    const u64 CBR = bc2(cbr), CBI = bc2(cbi), NBI = bc2(-cbi);
    #pragma unroll
    for (int s = 0; s < 8; ++s) {
        u64 pr = shfl2x(VR[s], 1 << j), pi = shfl2x(VI[s], 1 << j);
        u64 nr = f2fma(NBI, pi, f2fma(CBR, pr, f2fma(NAI, VI[s], f2mul(CAR, VR[s]))));
        u64 ni = f2fma(CBI, pr, f2fma(CBR, pi, f2fma(CAI, VR[s], f2mul(CAR, VI[s]))));
        VR[s] = nr; VI[s] = ni;
    }
}

// pass-B gates: rgate bits 5,6,7 + lgate bits 0..4 (pack = b15, never gated)
__device__ __forceinline__ void kb_gates(u64* VR, u64* VI, const float* gU, int lane) {
    rgateP<1>(VR, VI, gU + 40);
    rgateP<2>(VR, VI, gU + 48);
    rgateP<4>(VR, VI, gU + 56);
    #pragma unroll
    for (int j = 0; j < 5; ++j) lgateP(VR, VI, gU + j * 8, lane, j);
}

// pass-B store with full ladder perm folded in.
// dest low8 d = sfx8((k<<5)|lane) ^ (b8?255:0); b15' = b15 ^ d0.
__device__ __forceinline__ void kb_store(u64* VR, u64* VI, unsigned base,
                                         int cc, int w, int lane) {
    const int b8 = w & 1;
    const int S  = sfx5(lane);
    const int pl = __popc((unsigned)lane) & 1;
    #pragma unroll
    for (int k = 0; k < 8; ++k) {
        const int pk  = __popc((unsigned)k) & 1;                 // compile-time
        const int s3  = (k ^ (k >> 1) ^ (k >> 2)) & 7;           // sfx3(k), ct
        int flip = pk ^ b8;                                      // warp-uniform
        int dlo  = S ^ (flip ? 31 : 0);
        int dh3  = s3 ^ (b8 ? 7 : 0);
        int d0   = pl ^ flip;                                    // per lane
        float r0, r1, i0, i1;
        upk2(VR[k], r0, r1); upk2(VI[k], i0, i1);
        float Ar = d0 ? r1 : r0, Ai = d0 ? i1 : i0;              // dest b15'=0
        float Br = d0 ? r0 : r1, Bi = d0 ? i0 : i1;              // dest b15'=1
        unsigned a = base | (cc << 12) | (w << 8) | (dh3 << 5) | dlo;
        st_h2(&g_st[a], Ar, Ai);
        st_h2(&g_st[a | 0x8000u], Br, Bi);
    }
}

// ---------------------------------------------------------------------------
// Pass A (layers 1..3), PERSISTENT: grid-stride over 4096 tiles (b, c3).
// Lanes = bits 0..4, c3 = bits 5..7. Stage1: warp w = bits 12..15,
// slots = bits 8..10, pack = bit 11. Stage2 (after SMEM exchange):
// slots = bits 12..14, pack = bit 15. sfx8 perm folded into store address.
// ---------------------------------------------------------------------------
__global__ void __launch_bounds__(TPB, 2) kA(const float* __restrict__ par, int layer) {
    extern __shared__ float2 buf[];               // 8192 float2 = 64KB
    float* gU = (float*)(buf + 8192);             // 64 floats

    const int tid = threadIdx.x, lane = tid & 31, w = tid >> 5;

    if (tid < 8) compute_gate(par, layer, 7 - tid, gU + tid * 8);  // bit 8+j -> cq 7-j
    __syncthreads();                               // gU visible

    int sw = w ^ (w >> 1); sw ^= (sw >> 2);
    const int dwA = sw, dwB = sw ^ 15;

    for (int t = blockIdx.x; t < NTILES; t += gridDim.x) {
        const int c3 = t & 7;
        const unsigned base = (unsigned)(t >> 3) << 16;

        u64 VR[8], VI[8];
        #pragma unroll
        for (int k = 0; k < 8; ++k) {
            unsigned g0 = base | (w << 12) | (k << 8) | (c3 << 5) | lane;
            float ar, ai, br, bi;
            ld_h2(&g_st[g0], ar, ai);
            ld_h2(&g_st[g0 | (8u << 8)], br, bi);
            VR[k] = pk2(ar, br); VI[k] = pk2(ai, bi);
        }

        // stage1: gates bits 8,9,10 (slots) + 11 (pack)
        rgateP<1>(VR, VI, gU + 0);
        rgateP<2>(VR, VI, gU + 8);
        rgateP<4>(VR, VI, gU + 16);
        pgateP(VR, VI, gU + 24);

        __syncthreads();      // buf free (previous iteration's readers done)
        #pragma unroll
        for (int k = 0; k < 8; ++k) {
            float r0, r1, i0, i1;
            upk2(VR[k], r0, r1); upk2(VI[k], i0, i1);
            buf[(k * 16 + w) * 32 + lane]       = make_float2(r0, i0);
            buf[((8 | k) * 16 + w) * 32 + lane] = make_float2(r1, i1);
        }
        __syncthreads();
        #pragma unroll
        for (int k = 0; k < 8; ++k) {
            float2 a = buf[(w * 16 + k) * 32 + lane];        // e8=w, e12=k
            float2 b = buf[(w * 16 + (8 | k)) * 32 + lane];  // e12=8|k
            VR[k] = pk2(a.x, b.x); VI[k] = pk2(a.y, b.y);
        }

        // stage2: gates bits 12,13,14 (slots) + 15 (pack)
        rgateP<1>(VR, VI, gU + 32);
        rgateP<2>(VR, VI, gU + 40);
        rgateP<4>(VR, VI, gU + 48);
        pgateP(VR, VI, gU + 56);

        // store with sfx8 perm on hi bits folded in
        #pragma unroll
        for (int k = 0; k < 8; ++k) {
            float r0, r1, i0, i1;
            upk2(VR[k], r0, r1); upk2(VI[k], i0, i1);
            #pragma unroll
            for (int h = 0; h < 2; ++h) {
                int e12 = (h << 3) | k;
                int d12 = e12 ^ (e12 >> 1); d12 ^= (d12 >> 2);
                int dw  = (__popc((unsigned)e12) & 1) ? dwB : dwA;
                unsigned g = base | (d12 << 12) | (dw << 8) | (c3 << 5) | lane;
                st_h2(&g_st[g], h ? r1 : r0, h ? i1 : i0);
            }
        }
    }
}

// ---------------------------------------------------------------------------
// kB0 (layer 0): synthesize state (product state after RX init + layer-0 hi
// gates + hi perm) from tables, then layer-0 lo gates + perm + store.
// ---------------------------------------------------------------------------
__global__ void __launch_bounds__(TPB, 2) kB0(const float* __restrict__ x,
                                              const float* __restrict__ par) {
    __shared__ float4 fv[16];      // per-qubit 2-vec factors (complex pairs)
    __shared__ float  gU[64];
    __shared__ float2 Tlo[256], Thi[256];

    const int tid = threadIdx.x, lane = tid & 31, w = tid >> 5;  // w = bits 8..11
    const int cc  = blockIdx.x;
    const unsigned base = (unsigned)blockIdx.y << 16;

    if (tid < 16) {
        int m = tid;                         // index bit m <-> cq 15-m
        float s, c; sincosf(0.5f * x[blockIdx.y * 16 + (15 - m)], &s, &c);
        if (m < 8) {
            fv[m] = make_float4(c, 0.f, 0.f, -s);          // RX|0> = (c, -i s)
        } else {
            float U[8]; compute_gate(par, 0, 15 - m, U);   // layer-0 hi gate
            fv[m] = make_float4(U[0]*c + U[3]*s, U[1]*c - U[2]*s,
                                U[4]*c + U[7]*s, U[5]*c - U[6]*s);
        }
    } else if (tid >= 32 && tid < 40) {
        compute_gate(par, 0, 15 - (tid - 32), gU + (tid - 32) * 8);  // lo gates
    }
    __syncthreads();

    {   // build tables: threads 0..255 -> Tlo, 256..511 -> Thi (perm-relabeled)
        int e = tid & 255;
        int mbase = (tid < 256) ? 0 : 8;
        float2 cacc = make_float2(1.f, 0.f);
        #pragma unroll
        for (int m = 0; m < 8; ++m) {
            float4 F = fv[mbase + m];
            float2 bb = ((e >> m) & 1) ? make_float2(F.z, F.w)
                                       : make_float2(F.x, F.y);
            cacc = cmulf(cacc, bb);
        }
        if (tid < 256) {
            Tlo[e] = cacc;
        } else {
            int d = e ^ (e >> 1); d ^= d >> 2; d ^= d >> 4;   // sfx8(e)
            Thi[d & 255] = cacc;                              // Thi[h]=F(inv(h))
        }
    }
    __syncthreads();

    u64 VR[8], VI[8];
    float2 H0 = Thi[w | (cc << 4)];
    float2 H1 = Thi[w | (cc << 4) | 128];
    #pragma unroll
    for (int k = 0; k < 8; ++k) {
        float2 L  = Tlo[(k << 5) | lane];
        float2 a0 = cmulf(H0, L), a1 = cmulf(H1, L);
        VR[k] = pk2(a0.x, a1.x); VI[k] = pk2(a0.y, a1.y);
    }

    kb_gates(VR, VI, gU, lane);
    kb_store(VR, VI, base, cc, w, lane);
}

// ---------------------------------------------------------------------------
// kBmid (layers 1,2), PERSISTENT: grid-stride over 4096 tiles (b, cc),
// loop body barrier-free.
// ---------------------------------------------------------------------------
__global__ void __launch_bounds__(TPB, 2) kBmid(const float* __restrict__ par, int layer) {
    __shared__ float gU[64];

    const int tid = threadIdx.x, lane = tid & 31, w = tid >> 5;

    if (tid < 8) compute_gate(par, layer, 15 - tid, gU + tid * 8);
    __syncthreads();

    for (int t = blockIdx.x; t < NTILES; t += gridDim.x) {
        const int cc = t & 7;
        const unsigned base = (unsigned)(t >> 3) << 16;

        u64 VR[8], VI[8];
        #pragma unroll
        for (int k = 0; k < 8; ++k) {
            unsigned a = base | (cc << 12) | (w << 8) | (k << 5) | lane;
            float r0, i0, r1, i1;
            ld_h2(&g_st[a], r0, i0);
            ld_h2(&g_st[a | 0x8000u], r1, i1);
            VR[k] = pk2(r0, r1); VI[k] = pk2(i0, i1);
        }

        kb_gates(VR, VI, gU, lane);
        kb_store(VR, VI, base, cc, w, lane);
    }
}

// ---------------------------------------------------------------------------
// kBlast (layer 3), PERSISTENT: lo gates, then <Z> partials with perm folded
// analytically; per-tile reduction into g_part.
// ---------------------------------------------------------------------------
__global__ void __launch_bounds__(TPB, 2) kBlast(const float* __restrict__ par, int layer) {
    __shared__ float gU[64];
    __shared__ float red[16][17];

    const int tid = threadIdx.x, lane = tid & 31, w = tid >> 5;
    const int b8 = w & 1;

    if (tid < 8) compute_gate(par, layer, 15 - tid, gU + tid * 8);
    __syncthreads();

    const int S  = sfx5(lane);
    const int pl = __popc((unsigned)lane) & 1;

    for (int t = blockIdx.x; t < NTILES; t += gridDim.x) {
        const int cc = t & 7;
        const int b  = t >> 3;
        const unsigned base = (unsigned)b << 16;

        u64 VR[8], VI[8];
        #pragma unroll
        for (int k = 0; k < 8; ++k) {
            unsigned a = base | (cc << 12) | (w << 8) | (k << 5) | lane;
            float r0, i0, r1, i1;
            ld_h2(&g_st[a], r0, i0);
            ld_h2(&g_st[a | 0x8000u], r1, i1);
            VR[k] = pk2(r0, r1); VI[k] = pk2(i0, i1);
        }

        kb_gates(VR, VI, gU, lane);

        // probabilities; ee indexed by j0 = sfx3(k) (ct); W0 with (-1)^par(k)
        float ee[8], W0 = 0.f;
        #pragma unroll
        for (int k = 0; k < 8; ++k) {
            const int j0 = (k ^ (k >> 1) ^ (k >> 2)) & 7;
            const int pk = __popc((unsigned)k) & 1;
            float r0, r1, i0, i1;
            upk2(VR[k], r0, r1); upk2(VI[k], i0, i1);
            float p0 = r0 * r0 + i0 * i0, p1 = r1 * r1 + i1 * i1;
            ee[j0] = p0 + p1;
            W0 += pk ? (p1 - p0) : (p0 - p1);
        }
        // Walsh tree over ee (dest bits 5..7, pre b8-relabel)
        float e04 = ee[0] + ee[4], e15 = ee[1] + ee[5];
        float e26 = ee[2] + ee[6], e37 = ee[3] + ee[7];
        float T7 = (ee[0] - ee[4]) + (ee[1] - ee[5]) + (ee[2] - ee[6]) + (ee[3] - ee[7]);
        float a0 = e04 + e26, a1 = e15 + e37;
        float T6 = (e04 - e26) + (e15 - e37);
        float T0 = a0 + a1, T5 = a0 - a1;
        if (b8) { T5 = -T5; T6 = -T6; T7 = -T7; W0 = -W0; }  // j -> j^7

        float acc[16];
        #pragma unroll
        for (int m = 0; m < 16; ++m) {
            if      (m < 5)   acc[m] = ((S >> m) & 1) ? -T5 : T5;
            else if (m == 5)  acc[m] = T5;
            else if (m == 6)  acc[m] = T6;
            else if (m == 7)  acc[m] = T7;
            else if (m < 12)  acc[m] = ((w >> (m - 8)) & 1) ? -T0 : T0;
            else if (m < 15)  acc[m] = ((cc >> (m - 12)) & 1) ? -T0 : T0;
            else              acc[m] = pl ? -W0 : W0;
        }

        #pragma unroll
        for (int m = 0; m < 16; ++m) {
            float v = acc[m];
            #pragma unroll
            for (int o = 16; o > 0; o >>= 1) v += __shfl_xor_sync(0xffffffffu, v, o);
            if (lane == 0) red[m][w] = v;
        }
        __syncthreads();
        if (tid < 16) {
            float s = 0.f;
            #pragma unroll
            for (int k = 0; k < 16; ++k) s += red[tid][k];
            g_part[(b * 8 + cc) * 16 + tid] = s;
        }
        __syncthreads();   // red[] reuse guard for next tile
    }
}

__global__ void kBfin(float* __restrict__ out) {
    int i = blockIdx.x * blockDim.x + threadIdx.x;
    if (i < BAT * 16) {
        int b = i >> 4, m = i & 15;
        float s = 0.f;
        #pragma unroll
        for (int cc = 0; cc < 8; ++cc) s += g_part[(b * 8 + cc) * 16 + m];
        out[b * 16 + (15 - m)] = s;
    }
}

// ---------------------------------------------------------------------------
extern "C" void kernel_launch(void* const* d_in, const int* in_sizes, int n_in,
                              void* d_out, int out_size) {
    const float* x   = (const float*)d_in[0];
    const float* par = (const float*)d_in[1];
    if (n_in >= 2 && in_sizes[0] == 192) {
        const float* t = x; x = par; par = t;
    }
    float* out = (float*)d_out;

    int nsm = 148;
    cudaDeviceGetAttribute(&nsm, cudaDevAttrMultiProcessorCount, 0);
    const int gpersist = 2 * nsm;                 // exactly the 2-CTA/SM cap

    const size_t smA = 8192 * sizeof(float2) + 64 * sizeof(float);
    cudaFuncSetAttribute(kA, cudaFuncAttributeMaxDynamicSharedMemorySize, (int)smA);

    dim3 grid8(8, BAT);
    kB0<<<grid8, TPB>>>(x, par);                  // layer 0 (A analytic + B)
    for (int layer = 1; layer < 4; ++layer) {
        kA<<<gpersist, TPB, smA>>>(par, layer);
        if (layer < 3) {
            kBmid<<<gpersist, TPB>>>(par, layer);
        } else {
            kBlast<<<gpersist, TPB>>>(par, layer);
            kBfin<<<32, 256>>>(out);
        }
    }
}

// round 10
// speedup vs baseline: 1.1042x; 1.0113x over previous
#include <cuda_runtime.h>
#include <cuda_fp16.h>
#include <math.h>

// ---------------------------------------------------------------------------
// 16-qubit statevector, batch 512. circuit qubit i <-> index bit (15-i).
// Layer = 16 one-qubit gates + CNOT-ladder = suffix-XOR permutation.
// State between passes: __half2(re,im), fp32 compute (f32x2 packed FMA).
// All gates are SU(2): stored as 4 floats (u00r,u00i,u01r,u01i);
//   u10 = -conj(u01), u11 = conj(u00) derived inline (fewer const preps).
// kA: pack = lo bit 0 (ungated in pass A) -> vectorized 8B loads/stores,
//   no scalar pgate; two rgate stages + float4 SMEM exchange; sfx8 perm on
//   bits 8..15 folded into store address via precomputed XOR.
// kB: lane = bits 0..4, slots = bits 5..7, pack = b15 (ungated), warp = bits
//   8..11; ladder perm on bits 0..7 + b15-wrap folded into store.
// Persistent grids (2 x #SM) for kA/kBmid/kBlast.
// ---------------------------------------------------------------------------

#define TPB 512
#define BAT 512
#define NTILES 4096

typedef unsigned long long u64;

__device__ __half2 g_st[(size_t)BAT * 65536];
__device__ float   g_part[BAT * 8 * 16];

// ---------------- packed f32x2 helpers ----------------
__device__ __forceinline__ u64 pk2(float x, float y) {
    u64 r; asm("mov.b64 %0,{%1,%2};" : "=l"(r) : "f"(x), "f"(y)); return r;
}
__device__ __forceinline__ void upk2(u64 v, float& x, float& y) {
    asm("mov.b64 {%0,%1},%2;" : "=f"(x), "=f"(y) : "l"(v));
}
__device__ __forceinline__ u64 bc2(float x) { return pk2(x, x); }
__device__ __forceinline__ u64 f2mul(u64 a, u64 b) {
    u64 r; asm("mul.rn.f32x2 %0,%1,%2;" : "=l"(r) : "l"(a), "l"(b)); return r;
}
__device__ __forceinline__ u64 f2fma(u64 a, u64 b, u64 c) {
    u64 r; asm("fma.rn.f32x2 %0,%1,%2,%3;" : "=l"(r) : "l"(a), "l"(b), "l"(c)); return r;
}
__device__ __forceinline__ u64 shfl2x(u64 v, int m) {
    float x, y; upk2(v, x, y);
    x = __shfl_xor_sync(0xffffffffu, x, m);
    y = __shfl_xor_sync(0xffffffffu, y, m);
    return pk2(x, y);
}
__device__ __forceinline__ void ld_h2(const __half2* p, float& re, float& im) {
    float2 v = __half22float2(*p); re = v.x; im = v.y;
}
__device__ __forceinline__ void st_h2(__half2* p, float re, float im) {
    *p = __floats2half2_rn(re, im);
}
__device__ __forceinline__ float2 cmulf(float2 a, float2 b) {
    return make_float2(a.x * b.x - a.y * b.y, a.x * b.y + a.y * b.x);
}
__device__ __forceinline__ int sfx5(int v) {
    v ^= v >> 1; v ^= v >> 2; v ^= v >> 4; return v & 31;
}

// SU(2) gate U = Ry(p2)*Rx(p1)*Rz(p0): store row0 only (u00r,u00i,u01r,u01i)
__device__ __forceinline__ void compute_gate4(const float* __restrict__ par,
                                              int layer, int cq, float* uo) {
    const float* pp = par + ((layer * 16 + cq) * 3);
    float sz, cz, sx, cx_, sy, cy;
    sincosf(0.5f * pp[0], &sz, &cz);
    sincosf(0.5f * pp[1], &sx, &cx_);
    sincosf(0.5f * pp[2], &sy, &cy);
    float M00r =  cx_ * cz, M00i = -cx_ * sz;
    float M01r =  sx  * sz, M01i = -sx  * cz;
    float M10r = -sx  * sz, M10i = -sx  * cz;
    float M11r =  cx_ * cz, M11i =  cx_ * sz;
    uo[0] = cy * M00r - sy * M10r;  uo[1] = cy * M00i - sy * M10i;
    uo[2] = cy * M01r - sy * M11r;  uo[3] = cy * M01i - sy * M11i;
}

// packed SU(2) gate on slot bit B: new_a = alpha a + beta b; new_b = -beta* a + alpha* b
template<int B>
__device__ __forceinline__ void rgateP4(u64* VR, u64* VI, const float* __restrict__ u) {
    const u64 U0 = bc2(u[0]), U1 = bc2(u[1]), N1 = bc2(-u[1]);
    const u64 U2 = bc2(u[2]), N2 = bc2(-u[2]);
    const u64 U3 = bc2(u[3]), N3 = bc2(-u[3]);
    #pragma unroll
    for (int s = 0; s < 8; ++s) if (!(s & B)) {
        u64 ar = VR[s], ai = VI[s], br = VR[s | B], bi = VI[s | B];
        VR[s]     = f2fma(N3, bi, f2fma(U2, br, f2fma(N1, ai, f2mul(U0, ar))));
        VI[s]     = f2fma(U3, br, f2fma(U2, bi, f2fma(U1, ar, f2mul(U0, ai))));
        VR[s | B] = f2fma(U1, bi, f2fma(U0, br, f2fma(N3, ai, f2mul(N2, ar))));
        VI[s | B] = f2fma(N1, br, f2fma(U0, bi, f2fma(U3, ar, f2mul(N2, ai))));
    }
}

// packed SU(2) gate on lane bit j (shfl butterfly)
__device__ __forceinline__ void lgateP4(u64* VR, u64* VI, const float* __restrict__ u,
                                        int lane, int j) {
    const int hi = (lane >> j) & 1;
    const float cai = hi ? -u[1] : u[1];
    const float cbr = hi ? -u[2] : u[2];
    const u64 CAR = bc2(u[0]), CAI = bc2(cai), NAI = bc2(-cai);
    const u64 CBR = bc2(cbr), CBI = bc2(u[3]), NBI = bc2(-u[3]);
    #pragma unroll
    for (int s = 0; s < 8; ++s) {
        u64 pr = shfl2x(VR[s], 1 << j), pi = shfl2x(VI[s], 1 << j);
        u64 nr = f2fma(NBI, pi, f2fma(CBR, pr, f2fma(NAI, VI[s], f2mul(CAR, VR[s]))));
        u64 ni = f2fma(CBI, pr, f2fma(CBR, pi, f2fma(CAI, VR[s], f2mul(CAR, VI[s]))));
        VR[s] = nr; VI[s] = ni;
    }
}

// pass-B gates: rgate bits 5,6,7 + lgate bits 0..4 (pack = b15, never gated)
__device__ __forceinline__ void kb_gates(u64* VR, u64* VI, const float* gU, int lane) {
    rgateP4<1>(VR, VI, gU + 20);
    rgateP4<2>(VR, VI, gU + 24);
    rgateP4<4>(VR, VI, gU + 28);
    #pragma unroll
    for (int j = 0; j < 5; ++j) lgateP4(VR, VI, gU + j * 4, lane, j);
}

// pass-B store with full ladder perm folded in.
__device__ __forceinline__ void kb_store(u64* VR, u64* VI, unsigned base,
                                         int cc, int w, int lane) {
    const int b8 = w & 1;
    const int S  = sfx5(lane);
    const int pl = __popc((unsigned)lane) & 1;
    #pragma unroll
    for (int k = 0; k < 8; ++k) {
        const int pk  = __popc((unsigned)k) & 1;                 // compile-time
        const int s3  = (k ^ (k >> 1) ^ (k >> 2)) & 7;           // sfx3(k), ct
        int flip = pk ^ b8;                                      // warp-uniform
        int dlo  = S ^ (flip ? 31 : 0);
        int dh3  = s3 ^ (b8 ? 7 : 0);
        int d0   = pl ^ flip;                                    // per lane
        float r0, r1, i0, i1;
        upk2(VR[k], r0, r1); upk2(VI[k], i0, i1);
        float Ar = d0 ? r1 : r0, Ai = d0 ? i1 : i0;              // dest b15'=0
        float Br = d0 ? r0 : r1, Bi = d0 ? i0 : i1;              // dest b15'=1
        unsigned a = base | (cc << 12) | (w << 8) | (dh3 << 5) | dlo;
        st_h2(&g_st[a], Ar, Ai);
        st_h2(&g_st[a | 0x8000u], Br, Bi);
    }
}

// ---------------------------------------------------------------------------
// Pass A (layers 1..3), PERSISTENT. Tile = bits {0..4} U {8..15}, c3 = 5..7.
// pack = bit 0 (ungated). lane: llo = bits 1..4, b8/b12 = lane>>4.
// Stage1: warp = bits 12..15, slots = bits 9..11 (rgate), bit 8 = lgate(j=4).
// Stage2 (after float4 SMEM exchange): warp = bits 8..11, slots = 13..15,
//   bit 12 = lgate(j=4). sfx8 perm on bits 8..15 folded into store address.
// ---------------------------------------------------------------------------
__global__ void __launch_bounds__(TPB, 2) kA(const float* __restrict__ par, int layer) {
    extern __shared__ float4 buf4[];              // 4096 float4 = 64KB
    float* gUA = (float*)(buf4 + 4096);           // 32 floats

    const int tid = threadIdx.x, lane = tid & 31, w = tid >> 5;
    if (tid < 8) compute_gate4(par, layer, 7 - tid, gUA + tid * 4);  // bit 8+j
    __syncthreads();

    const int llo = lane & 15, bh = lane >> 4;        // bh = b8 (st1) / b12 (st2)
    const int wbase = bh * 256 + w * 16 + llo;        // write: [(k<<1)|b8][w][llo]
    const int rbase = w * 256 + bh * 16 + llo;        // read:  [w][(k<<1)|b12][llo]
    int R = w | (bh << 4);                            // stage2 hi bits 8..12
    int GR = R ^ (R >> 1); GR ^= GR >> 2; GR ^= GR >> 4;  // sfx8(R)

    for (int t = blockIdx.x; t < NTILES; t += gridDim.x) {
        const int c3 = t & 7;
        const unsigned base = (unsigned)(t >> 3) << 16;
        const unsigned aL = base | (w << 12) | (bh << 8) | (c3 << 5) | (llo << 1);

        u64 VR[8], VI[8];
        #pragma unroll
        for (int k = 0; k < 8; ++k) {
            uint2 raw = *reinterpret_cast<const uint2*>(g_st + (aL | (k << 9)));
            float2 f0 = __half22float2(*reinterpret_cast<__half2*>(&raw.x));
            float2 f1 = __half22float2(*reinterpret_cast<__half2*>(&raw.y));
            VR[k] = pk2(f0.x, f1.x); VI[k] = pk2(f0.y, f1.y);
        }

        // stage1: bits 9,10,11 (rgate) + bit 8 (lane gate j=4)
        rgateP4<1>(VR, VI, gUA + 4);
        rgateP4<2>(VR, VI, gUA + 8);
        rgateP4<4>(VR, VI, gUA + 12);
        lgateP4(VR, VI, gUA + 0, lane, 4);

        __syncthreads();     // buf4 free (prev iteration's readers done)
        #pragma unroll
        for (int k = 0; k < 8; ++k) {
            float r0, r1, i0, i1;
            upk2(VR[k], r0, r1); upk2(VI[k], i0, i1);
            buf4[wbase + k * 512] = make_float4(r0, i0, r1, i1);
        }
        __syncthreads();
        #pragma unroll
        for (int k = 0; k < 8; ++k) {
            float4 v = buf4[rbase + k * 32];
            VR[k] = pk2(v.x, v.z); VI[k] = pk2(v.y, v.w);
        }

        // stage2: bits 13,14,15 (rgate) + bit 12 (lane gate j=4)
        rgateP4<1>(VR, VI, gUA + 20);
        rgateP4<2>(VR, VI, gUA + 24);
        rgateP4<4>(VR, VI, gUA + 28);
        lgateP4(VR, VI, gUA + 16, lane, 4);

        // store: dest hi byte = GR ^ sfx8(k<<5); lo bits unchanged (8B store)
        const unsigned D0 = base | ((unsigned)GR << 8) | (c3 << 5) | (llo << 1);
        #pragma unroll
        for (int k = 0; k < 8; ++k) {
            int e = k << 5; e ^= e >> 1; e ^= e >> 2; e ^= e >> 4;   // ct
            unsigned idx = D0 ^ ((unsigned)e << 8);
            float r0, r1, i0, i1;
            upk2(VR[k], r0, r1); upk2(VI[k], i0, i1);
            __half2 ha = __floats2half2_rn(r0, i0);
            __half2 hb = __floats2half2_rn(r1, i1);
            uint2 o;
            o.x = *reinterpret_cast<unsigned*>(&ha);
            o.y = *reinterpret_cast<unsigned*>(&hb);
            *reinterpret_cast<uint2*>(g_st + idx) = o;
        }
    }
}

// ---------------------------------------------------------------------------
// kB0 (layer 0): synthesize state (product state after RX init + layer-0 hi
// gates + hi perm) from tables, then layer-0 lo gates + perm + store.
// ---------------------------------------------------------------------------
__global__ void __launch_bounds__(TPB, 2) kB0(const float* __restrict__ x,
                                              const float* __restrict__ par) {
    __shared__ float4 fv[16];      // per-qubit 2-vec factors (complex pairs)
    __shared__ float  gU[32];
    __shared__ float2 Tlo[256], Thi[256];

    const int tid = threadIdx.x, lane = tid & 31, w = tid >> 5;  // w = bits 8..11
    const int cc  = blockIdx.x;
    const unsigned base = (unsigned)blockIdx.y << 16;

    if (tid < 16) {
        int m = tid;                         // index bit m <-> cq 15-m
        float s, c; sincosf(0.5f * x[blockIdx.y * 16 + (15 - m)], &s, &c);
        if (m < 8) {
            fv[m] = make_float4(c, 0.f, 0.f, -s);          // RX|0> = (c, -i s)
        } else {
            float U[4]; compute_gate4(par, 0, 15 - m, U);  // layer-0 hi gate
            fv[m] = make_float4(U[0]*c + U[3]*s, U[1]*c - U[2]*s,
                                -U[2]*c - U[1]*s, U[3]*c - U[0]*s);
        }
    } else if (tid >= 32 && tid < 40) {
        compute_gate4(par, 0, 15 - (tid - 32), gU + (tid - 32) * 4);  // lo gates
    }
    __syncthreads();

    {   // build tables: threads 0..255 -> Tlo, 256..511 -> Thi (perm-relabeled)
        int e = tid & 255;
        int mbase = (tid < 256) ? 0 : 8;
        float2 cacc = make_float2(1.f, 0.f);
        #pragma unroll
        for (int m = 0; m < 8; ++m) {
            float4 F = fv[mbase + m];
            float2 bb = ((e >> m) & 1) ? make_float2(F.z, F.w)
                                       : make_float2(F.x, F.y);
            cacc = cmulf(cacc, bb);
        }
        if (tid < 256) {
            Tlo[e] = cacc;
        } else {
            int d = e ^ (e >> 1); d ^= d >> 2; d ^= d >> 4;   // sfx8(e)
            Thi[d & 255] = cacc;                              // Thi[h]=F(inv(h))
        }
    }
    __syncthreads();

    u64 VR[8], VI[8];
    float2 H0 = Thi[w | (cc << 4)];
    float2 H1 = Thi[w | (cc << 4) | 128];
    #pragma unroll
    for (int k = 0; k < 8; ++k) {
        float2 L  = Tlo[(k << 5) | lane];
        float2 a0 = cmulf(H0, L), a1 = cmulf(H1, L);
        VR[k] = pk2(a0.x, a1.x); VI[k] = pk2(a0.y, a1.y);
    }

    kb_gates(VR, VI, gU, lane);
    kb_store(VR, VI, base, cc, w, lane);
}

// ---------------------------------------------------------------------------
// kBmid (layers 1,2), PERSISTENT: load, lo gates, perm-folded store.
// ---------------------------------------------------------------------------
__global__ void __launch_bounds__(TPB, 2) kBmid(const float* __restrict__ par, int layer) {
    __shared__ float gU[32];

    const int tid = threadIdx.x, lane = tid & 31, w = tid >> 5;

    if (tid < 8) compute_gate4(par, layer, 15 - tid, gU + tid * 4);
    __syncthreads();

    for (int t = blockIdx.x; t < NTILES; t += gridDim.x) {
        const int cc = t & 7;
        const unsigned base = (unsigned)(t >> 3) << 16;

        u64 VR[8], VI[8];
        #pragma unroll
        for (int k = 0; k < 8; ++k) {
            unsigned a = base | (cc << 12) | (w << 8) | (k << 5) | lane;
            float r0, i0, r1, i1;
            ld_h2(&g_st[a], r0, i0);
            ld_h2(&g_st[a | 0x8000u], r1, i1);
            VR[k] = pk2(r0, r1); VI[k] = pk2(i0, i1);
        }

        kb_gates(VR, VI, gU, lane);
        kb_store(VR, VI, base, cc, w, lane);
    }
}

// ---------------------------------------------------------------------------
// kBlast (layer 3), PERSISTENT: lo gates, then <Z> partials (perm analytic).
// ---------------------------------------------------------------------------
__global__ void __launch_bounds__(TPB, 2) kBlast(const float* __restrict__ par, int layer) {
    __shared__ float gU[32];
    __shared__ float red[16][17];

    const int tid = threadIdx.x, lane = tid & 31, w = tid >> 5;
    const int b8 = w & 1;

    if (tid < 8) compute_gate4(par, layer, 15 - tid, gU + tid * 4);
    __syncthreads();

    const int S  = sfx5(lane);
    const int pl = __popc((unsigned)lane) & 1;

    for (int t = blockIdx.x; t < NTILES; t += gridDim.x) {
        const int cc = t & 7;
        const int b  = t >> 3;
        const unsigned base = (unsigned)b << 16;

        u64 VR[8], VI[8];
        #pragma unroll
        for (int k = 0; k < 8; ++k) {
            unsigned a = base | (cc << 12) | (w << 8) | (k << 5) | lane;
            float r0, i0, r1, i1;
            ld_h2(&g_st[a], r0, i0);
            ld_h2(&g_st[a | 0x8000u], r1, i1);
            VR[k] = pk2(r0, r1); VI[k] = pk2(i0, i1);
        }

        kb_gates(VR, VI, gU, lane);

        float ee[8], W0 = 0.f;
        #pragma unroll
        for (int k = 0; k < 8; ++k) {
            const int j0 = (k ^ (k >> 1) ^ (k >> 2)) & 7;
            const int pk = __popc((unsigned)k) & 1;
            float r0, r1, i0, i1;
            upk2(VR[k], r0, r1); upk2(VI[k], i0, i1);
            float p0 = r0 * r0 + i0 * i0, p1 = r1 * r1 + i1 * i1;
            ee[j0] = p0 + p1;
            W0 += pk ? (p1 - p0) : (p0 - p1);
        }
        float e04 = ee[0] + ee[4], e15 = ee[1] + ee[5];
        float e26 = ee[2] + ee[6], e37 = ee[3] + ee[7];
        float T7 = (ee[0] - ee[4]) + (ee[1] - ee[5]) + (ee[2] - ee[6]) + (ee[3] - ee[7]);
        float a0 = e04 + e26, a1 = e15 + e37;
        float T6 = (e04 - e26) + (e15 - e37);
        float T0 = a0 + a1, T5 = a0 - a1;
        if (b8) { T5 = -T5; T6 = -T6; T7 = -T7; W0 = -W0; }

        float acc[16];
        #pragma unroll
        for (int m = 0; m < 16; ++m) {
            if      (m < 5)   acc[m] = ((S >> m) & 1) ? -T5 : T5;
            else if (m == 5)  acc[m] = T5;
            else if (m == 6)  acc[m] = T6;
            else if (m == 7)  acc[m] = T7;
            else if (m < 12)  acc[m] = ((w >> (m - 8)) & 1) ? -T0 : T0;
            else if (m < 15)  acc[m] = ((cc >> (m - 12)) & 1) ? -T0 : T0;
            else              acc[m] = pl ? -W0 : W0;
        }

        #pragma unroll
        for (int m = 0; m < 16; ++m) {
            float v = acc[m];
            #pragma unroll
            for (int o = 16; o > 0; o >>= 1) v += __shfl_xor_sync(0xffffffffu, v, o);
            if (lane == 0) red[m][w] = v;
        }
        __syncthreads();
        if (tid < 16) {
            float s = 0.f;
            #pragma unroll
            for (int k = 0; k < 16; ++k) s += red[tid][k];
            g_part[(b * 8 + cc) * 16 + tid] = s;
        }
        __syncthreads();
    }
}

__global__ void kBfin(float* __restrict__ out) {
    int i = blockIdx.x * blockDim.x + threadIdx.x;
    if (i < BAT * 16) {
        int b = i >> 4, m = i & 15;
        float s = 0.f;
        #pragma unroll
        for (int cc = 0; cc < 8; ++cc) s += g_part[(b * 8 + cc) * 16 + m];
        out[b * 16 + (15 - m)] = s;
    }
}

// ---------------------------------------------------------------------------
extern "C" void kernel_launch(void* const* d_in, const int* in_sizes, int n_in,
                              void* d_out, int out_size) {
    const float* x   = (const float*)d_in[0];
    const float* par = (const float*)d_in[1];
    if (n_in >= 2 && in_sizes[0] == 192) {
        const float* t = x; x = par; par = t;
    }
    float* out = (float*)d_out;

    int nsm = 148;
    cudaDeviceGetAttribute(&nsm, cudaDevAttrMultiProcessorCount, 0);
    const int gpersist = 2 * nsm;

    const size_t smA = 4096 * sizeof(float4) + 32 * sizeof(float);
    cudaFuncSetAttribute(kA, cudaFuncAttributeMaxDynamicSharedMemorySize, (int)smA);

    dim3 grid8(8, BAT);
    kB0<<<grid8, TPB>>>(x, par);                  // layer 0 (A analytic + B)
    for (int layer = 1; layer < 4; ++layer) {
        kA<<<gpersist, TPB, smA>>>(par, layer);
        if (layer < 3) {
            kBmid<<<gpersist, TPB>>>(par, layer);
        } else {
            kBlast<<<gpersist, TPB>>>(par, layer);
            kBfin<<<32, 256>>>(out);
        }
    }
}